// round 16
// baseline (speedup 1.0000x reference)
#include <cuda_runtime.h>
#include <math.h>
#include <stdint.h>

#define NR 4096
#define MAXS 128
typedef unsigned long long ull;

// ---------------- scratch (device globals) ----------------
__device__ float g_z0[NR * MAXS], g_z1[NR * MAXS];   // z ping-pong, layout [s][r]
__device__ float g_s0[NR * MAXS], g_s1[NR * MAXS];   // sdf ping-pong
__device__ float g_newz[NR * 16], g_newsdf[NR * 16]; // [t][r]
__device__ float g_w[NR * MAXS];                     // upsample weights scratch
__device__ float g_fsdf[NR * MAXS], g_tc[NR * MAXS]; // final pass, [s][r]

// ---------------- scalar helpers ----------------
__device__ __forceinline__ ull pack2(float lo, float hi) {
    ull d; asm("mov.b64 %0, {%1, %2};" : "=l"(d) : "f"(lo), "f"(hi)); return d;
}
__device__ __forceinline__ void unpack2(ull v, float& lo, float& hi) {
    asm("mov.b64 {%0, %1}, %2;" : "=f"(lo), "=f"(hi) : "l"(v));
}
__device__ __forceinline__ ull ffma2(ull a, ull b, ull c) {
    ull d; asm("fma.rn.f32x2 %0, %1, %2, %3;" : "=l"(d) : "l"(a), "l"(b), "l"(c)); return d;
}
__device__ __forceinline__ ull fadd2(ull a, ull b) {
    ull d; asm("add.rn.f32x2 %0, %1, %2;" : "=l"(d) : "l"(a), "l"(b)); return d;
}
__device__ __forceinline__ float softplusf(float x) {
    return fmaxf(x, 0.f) + log1pf(expf(-fabsf(x)));
}
__device__ __forceinline__ float sigmoidf(float x) {
    return 1.f / (1.f + expf(-x));
}

// ---------------- tf32 mma.sync helpers (base-target PTX, sm_80+) ----------------
__device__ __forceinline__ uint32_t f2tf(float x) {
    uint32_t r; asm("cvt.rna.tf32.f32 %0, %1;" : "=r"(r) : "f"(x)); return r;
}
__device__ __forceinline__ void mma_tf32(float* d,
    uint32_t a0, uint32_t a1, uint32_t a2, uint32_t a3,
    uint32_t b0, uint32_t b1)
{
    asm volatile(
        "mma.sync.aligned.m16n8k8.row.col.f32.tf32.tf32.f32 "
        "{%0,%1,%2,%3}, {%4,%5,%6,%7}, {%8,%9}, {%0,%1,%2,%3};"
        : "+f"(d[0]), "+f"(d[1]), "+f"(d[2]), "+f"(d[3])
        : "r"(a0), "r"(a1), "r"(a2), "r"(a3), "r"(b0), "r"(b1));
}

// ---------------- init z (linspace, [s][r]) ----------------
__global__ void k_init_z(const float* __restrict__ near_, const float* __restrict__ far_) {
    int idx = blockIdx.x * blockDim.x + threadIdx.x;
    if (idx >= NR * 64) return;
    int r = idx & (NR - 1), s = idx >> 12;
    float t = (s == 63) ? 1.0f : s * (1.0f / 63.0f);
    g_z0[s * NR + r] = near_[r] + (far_[r] - near_[r]) * t;
}

// =====================================================================
// Scalar GEMM-structured forward MLP (R8, proven) for sampling phases.
// =====================================================================
#define SMEM_F (25984 * 4)

__device__ __forceinline__ void stage1_chunk(
    int c, int t, float* ATc, const float* W1s, const float* b1s,
    const float* xs, const float* ys, const float* zs)
{
    int p = t & 127, ih = t >> 7;
    float xv = xs[p], yv = ys[p], zv = zs[p];
    #pragma unroll 4
    for (int il = 32 * ih; il < 32 * ih + 32; il++) {
        int i = 64 * c + il;
        float a = fmaf(xv, W1s[i], fmaf(yv, W1s[128 + i], fmaf(zv, W1s[256 + i], b1s[i])));
        ATc[il * 132 + p] = softplusf(a);
    }
}

__device__ __forceinline__ void gemm_chunk(
    int c, int tp, int tj, const float* ATc, const float* W2s, ull acc[4][8])
{
    const ulonglong2* ATv = (const ulonglong2*)ATc;
    #pragma unroll 2
    for (int il = 0; il < 64; il++) {
        int i = 64 * c + il;
        ulonglong2 a01 = ATv[il * 33 + 2 * tp];
        ulonglong2 a23 = ATv[il * 33 + 2 * tp + 1];
        ull ws[8];
        #pragma unroll
        for (int q = 0; q < 8; q++) { float w = W2s[i * 128 + tj + 16 * q]; ws[q] = pack2(w, w); }
        #pragma unroll
        for (int q = 0; q < 8; q++) {
            acc[0][q] = ffma2(a01.x, ws[q], acc[0][q]);
            acc[1][q] = ffma2(a01.y, ws[q], acc[1][q]);
            acc[2][q] = ffma2(a23.x, ws[q], acc[2][q]);
            acc[3][q] = ffma2(a23.y, ws[q], acc[3][q]);
        }
    }
}

__global__ __launch_bounds__(256, 2) void k_mlp_fwd(
    const float* __restrict__ W1, const float* __restrict__ b1,
    const float* __restrict__ W2, const float* __restrict__ b2,
    const float* __restrict__ W3, const float* __restrict__ b3,
    const float* __restrict__ ro, const float* __restrict__ rd,
    int mode)
{
    extern __shared__ float sm[];
    float* W2s = sm;
    float* ATc = sm + 16384;
    float* W1s = sm + 24832;
    float* b1s = sm + 25216;
    float* b2s = sm + 25344;
    float* W3s = sm + 25472;
    float* xs  = sm + 25600;
    float* ys  = sm + 25728;
    float* zs  = sm + 25856;
    int t = threadIdx.x;

    for (int e = t; e < 16384; e += 256) W2s[e] = W2[e];
    for (int e = t; e < 384; e += 256) W1s[e] = W1[e];
    if (t < 128) { b1s[t] = b1[t]; b2s[t] = b2[t]; W3s[t] = W3[t]; }
    if (t < 128) {
        int gidx = blockIdx.x * 128 + t;
        int r = gidx & (NR - 1);
        float z = (mode == 0) ? g_z0[gidx] : g_newz[gidx];
        xs[t] = ro[3*r]   + rd[3*r]   * z;
        ys[t] = ro[3*r+1] + rd[3*r+1] * z;
        zs[t] = ro[3*r+2] + rd[3*r+2] * z;
    }
    __syncthreads();

    int tp = t >> 4, tj = t & 15;
    ull acc[4][8];
    #pragma unroll
    for (int pp = 0; pp < 4; pp++)
        #pragma unroll
        for (int q = 0; q < 8; q++) acc[pp][q] = 0;

    #pragma unroll 1
    for (int c = 0; c < 2; c++) {
        if (c) __syncthreads();
        stage1_chunk(c, t, ATc, W1s, b1s, xs, ys, zs);
        __syncthreads();
        gemm_chunk(c, tp, tj, ATc, W2s, acc);
    }

    ull sdfp[4] = {0, 0, 0, 0};
    #pragma unroll
    for (int q = 0; q < 8; q++) {
        int j = tj + 16*q;
        float b2j = b2s[j], w3j = W3s[j];
        ull w3p = pack2(w3j, w3j);
        #pragma unroll
        for (int pp = 0; pp < 4; pp++) {
            float alo, ahi; unpack2(acc[pp][q], alo, ahi);
            alo += b2j; ahi += b2j;
            sdfp[pp] = ffma2(pack2(softplusf(alo), softplusf(ahi)), w3p, sdfp[pp]);
        }
    }
    #pragma unroll
    for (int m = 1; m < 16; m <<= 1)
        #pragma unroll
        for (int pp = 0; pp < 4; pp++)
            sdfp[pp] = fadd2(sdfp[pp], __shfl_xor_sync(0xffffffffu, sdfp[pp], m, 16));
    if (tj == 0) {
        float b3v = b3[0];
        float* outb = (mode == 0) ? g_s0 : g_newsdf;
        int gb = blockIdx.x * 128 + 8*tp;
        #pragma unroll
        for (int pp = 0; pp < 4; pp++) {
            float lo, hi; unpack2(sdfp[pp], lo, hi);
            outb[gb + 2*pp]     = lo + b3v;
            outb[gb + 2*pp + 1] = hi + b3v;
        }
    }
}

// =====================================================================
// Fused final pass via mma.sync tf32 (3xTF32 split), base-target PTX.
// Block = 128-point tile, 8 warps. Warp (wm=w>>1, wn=w&1): 32p x 64 cols.
// GEMM1: a2[p][j] = sum_i h1[p][i] W2[i][j]   (A=h1 [p][i], B=W2 [i][j])
// GEMM2: g1[p][i] = sum_j g2[p][j] W2[i][j]   (A=g2 [p][j], B=W2^T [j][i])
// Fragments per PTX ISA m16n8k8 layout; smem strides 68/132 (=4 mod 32).
// =====================================================================
// smem float offsets
#define O_A1H 0        // 128 x 68  (h1 hi, chunk)
#define O_A1L 8704     // 128 x 68  (h1 lo)
#define O_B1H 17408    // 64 x 132  (W2 rows hi, chunk)
#define O_B1L 25856    // 64 x 132
#define O_A2H 0        // 128 x 132 (g2 hi, full)  -- reuses GEMM1 region
#define O_A2L 16896    // 128 x 132
#define O_B2H 33792    // 64 x 132  (W2^T hi, chunk)
#define O_B2L 42240    // 64 x 132
#define O_W1  50688
#define O_B1S 51072
#define O_B2S 51200
#define O_W3  51328
#define O_XS  51456
#define O_YS  51584
#define O_ZS  51712
#define O_DX  51840
#define O_DY  51968
#define O_DZ  52096
#define O_SDF 52224    // 2 x 128 partial sdf
#define O_GP  52480    // 2 x 128 x 3 partial grads
#define SMEM_FIN (53248 * 4)

__global__ __launch_bounds__(256, 1) void k_mlp_final(
    const float* __restrict__ W1, const float* __restrict__ b1,
    const float* __restrict__ W2, const float* __restrict__ b2,
    const float* __restrict__ W3, const float* __restrict__ b3,
    const float* __restrict__ ro, const float* __restrict__ rd,
    float* __restrict__ grad_out)
{
    extern __shared__ float sm[];
    int t = threadIdx.x;
    int lane = t & 31, w = t >> 5;
    int g = lane >> 2, q = lane & 3;
    int wm = w >> 1, wn = w & 1;

    float* W1s = sm + O_W1;
    float* b1s = sm + O_B1S;
    float* b2s = sm + O_B2S;
    float* W3s = sm + O_W3;
    float* xs = sm + O_XS; float* ys = sm + O_YS; float* zs = sm + O_ZS;

    for (int e = t; e < 384; e += 256) W1s[e] = W1[e];
    if (t < 128) { b1s[t] = b1[t]; b2s[t] = b2[t]; W3s[t] = W3[t]; }
    if (t < 128) {
        int gidx = blockIdx.x * 128 + t;
        int r = gidx & (NR - 1), s = gidx >> 12;
        float zk = g_z0[gidx];
        float dist = (s < 127) ? (g_z0[gidx + NR] - zk) : 0.03125f;  // SAMPLE_DIST
        float midz = zk + 0.5f * dist;
        float dx = rd[3*r], dy = rd[3*r+1], dz = rd[3*r+2];
        sm[O_DX + t] = dx; sm[O_DY + t] = dy; sm[O_DZ + t] = dz;
        xs[t] = ro[3*r]   + dx * midz;
        ys[t] = ro[3*r+1] + dy * midz;
        zs[t] = ro[3*r+2] + dz * midz;
    }
    __syncthreads();

    // ================= GEMM1: a2 = h1 @ W2 (k = i, 2 chunks of 64) =========
    float acc[2][8][4];
    #pragma unroll
    for (int mt = 0; mt < 2; mt++)
        #pragma unroll
        for (int nt = 0; nt < 8; nt++)
            #pragma unroll
            for (int e = 0; e < 4; e++) acc[mt][nt][e] = 0.f;

    #pragma unroll 1
    for (int c = 0; c < 2; c++) {
        if (c) __syncthreads();
        // stage A1c: h1[p][il] split hi/lo (recompute layer-1)
        for (int idx = t; idx < 8192; idx += 256) {
            int p = idx & 127, il = idx >> 7;
            int i = 64 * c + il;
            float a = fmaf(xs[p], W1s[i], fmaf(ys[p], W1s[128+i], fmaf(zs[p], W1s[256+i], b1s[i])));
            float h = softplusf(a);
            float hf = __uint_as_float(f2tf(h));
            sm[O_A1H + p * 68 + il] = hf;
            sm[O_A1L + p * 68 + il] = __uint_as_float(f2tf(h - hf));
        }
        // stage B1c: W2[64c+il][j] split hi/lo
        for (int idx = t; idx < 8192; idx += 256) {
            int j = idx & 127, il = idx >> 7;
            float v = W2[(64 * c + il) * 128 + j];
            float hf = __uint_as_float(f2tf(v));
            sm[O_B1H + il * 132 + j] = hf;
            sm[O_B1L + il * 132 + j] = __uint_as_float(f2tf(v - hf));
        }
        __syncthreads();

        const uint32_t* A1h = (const uint32_t*)(sm + O_A1H);
        const uint32_t* A1l = (const uint32_t*)(sm + O_A1L);
        const uint32_t* B1h = (const uint32_t*)(sm + O_B1H);
        const uint32_t* B1l = (const uint32_t*)(sm + O_B1L);
        #pragma unroll 2
        for (int kk = 0; kk < 8; kk++) {
            int kc = kk * 8 + q;
            uint32_t ah[2][4], al[2][4];
            #pragma unroll
            for (int mt = 0; mt < 2; mt++) {
                int r0 = (wm * 32 + mt * 16 + g) * 68;
                ah[mt][0] = A1h[r0 + kc];        al[mt][0] = A1l[r0 + kc];
                ah[mt][1] = A1h[r0 + 8*68 + kc]; al[mt][1] = A1l[r0 + 8*68 + kc];
                ah[mt][2] = A1h[r0 + kc + 4];    al[mt][2] = A1l[r0 + kc + 4];
                ah[mt][3] = A1h[r0 + 8*68 + kc + 4]; al[mt][3] = A1l[r0 + 8*68 + kc + 4];
            }
            uint32_t bh[8][2], bl[8][2];
            #pragma unroll
            for (int nt = 0; nt < 8; nt++) {
                int cb = wn * 64 + nt * 8 + g;
                bh[nt][0] = B1h[kc * 132 + cb];       bl[nt][0] = B1l[kc * 132 + cb];
                bh[nt][1] = B1h[(kc + 4) * 132 + cb]; bl[nt][1] = B1l[(kc + 4) * 132 + cb];
            }
            #pragma unroll
            for (int mt = 0; mt < 2; mt++)
                #pragma unroll
                for (int nt = 0; nt < 8; nt++) {
                    mma_tf32(acc[mt][nt], ah[mt][0], ah[mt][1], ah[mt][2], ah[mt][3], bh[nt][0], bh[nt][1]);
                    mma_tf32(acc[mt][nt], al[mt][0], al[mt][1], al[mt][2], al[mt][3], bh[nt][0], bh[nt][1]);
                    mma_tf32(acc[mt][nt], ah[mt][0], ah[mt][1], ah[mt][2], ah[mt][3], bl[nt][0], bl[nt][1]);
                }
        }
    }
    __syncthreads();   // all GEMM1 smem reads done before A2 overwrite

    // ================= epilogue A: sdf + g2 -> A2 tiles ====================
    {
        float sp[2][2] = {{0.f, 0.f}, {0.f, 0.f}};
        #pragma unroll
        for (int mt = 0; mt < 2; mt++)
            #pragma unroll
            for (int o = 0; o < 2; o++) {
                int rr = wm * 32 + mt * 16 + g + 8 * o;
                #pragma unroll
                for (int nt = 0; nt < 8; nt++)
                    #pragma unroll
                    for (int par = 0; par < 2; par++) {
                        int jj = wn * 64 + nt * 8 + 2 * q + par;
                        float a2 = acc[mt][nt][o * 2 + par] + b2s[jj];
                        float ex = expf(-fabsf(a2));
                        float h2 = fmaxf(a2, 0.f) + log1pf(ex);
                        float w3j = W3s[jj];
                        sp[mt][o] = fmaf(h2, w3j, sp[mt][o]);
                        float sig = (a2 >= 0.f) ? (1.f / (1.f + ex)) : (ex / (1.f + ex));
                        float g2 = sig * w3j;
                        float hf = __uint_as_float(f2tf(g2));
                        sm[O_A2H + rr * 132 + jj] = hf;
                        sm[O_A2L + rr * 132 + jj] = __uint_as_float(f2tf(g2 - hf));
                    }
            }
        #pragma unroll
        for (int mt = 0; mt < 2; mt++)
            #pragma unroll
            for (int o = 0; o < 2; o++) {
                sp[mt][o] += __shfl_xor_sync(0xffffffffu, sp[mt][o], 1);
                sp[mt][o] += __shfl_xor_sync(0xffffffffu, sp[mt][o], 2);
            }
        if (q == 0) {
            #pragma unroll
            for (int mt = 0; mt < 2; mt++)
                #pragma unroll
                for (int o = 0; o < 2; o++)
                    sm[O_SDF + wn * 128 + wm * 32 + mt * 16 + g + 8 * o] = sp[mt][o];
        }
    }
    __syncthreads();
    if (t < 128)
        g_fsdf[blockIdx.x * 128 + t] = b3[0] + sm[O_SDF + t] + sm[O_SDF + 128 + t];

    // ================= GEMM2: g1 = g2 @ W2^T (k = j, 2 chunks) =============
    float acc2[2][8][4];
    #pragma unroll
    for (int mt = 0; mt < 2; mt++)
        #pragma unroll
        for (int nt = 0; nt < 8; nt++)
            #pragma unroll
            for (int e = 0; e < 4; e++) acc2[mt][nt][e] = 0.f;

    #pragma unroll 1
    for (int c = 0; c < 2; c++) {
        if (c) __syncthreads();
        // stage B2c: W2^T[jl][i] = W2[i][64c+jl] split hi/lo
        for (int idx = t; idx < 8192; idx += 256) {
            int jl = idx & 63, i = idx >> 6;
            float v = W2[i * 128 + 64 * c + jl];
            float hf = __uint_as_float(f2tf(v));
            sm[O_B2H + jl * 132 + i] = hf;
            sm[O_B2L + jl * 132 + i] = __uint_as_float(f2tf(v - hf));
        }
        __syncthreads();

        const uint32_t* A2h = (const uint32_t*)(sm + O_A2H);
        const uint32_t* A2l = (const uint32_t*)(sm + O_A2L);
        const uint32_t* B2h = (const uint32_t*)(sm + O_B2H);
        const uint32_t* B2l = (const uint32_t*)(sm + O_B2L);
        #pragma unroll 2
        for (int kk = 0; kk < 8; kk++) {
            int kc = kk * 8 + q;                // col within chunk (A2 col = 64c + kc)
            uint32_t ah[2][4], al[2][4];
            #pragma unroll
            for (int mt = 0; mt < 2; mt++) {
                int r0 = (wm * 32 + mt * 16 + g) * 132 + 64 * c;
                ah[mt][0] = A2h[r0 + kc];          al[mt][0] = A2l[r0 + kc];
                ah[mt][1] = A2h[r0 + 8*132 + kc];  al[mt][1] = A2l[r0 + 8*132 + kc];
                ah[mt][2] = A2h[r0 + kc + 4];      al[mt][2] = A2l[r0 + kc + 4];
                ah[mt][3] = A2h[r0 + 8*132 + kc + 4]; al[mt][3] = A2l[r0 + 8*132 + kc + 4];
            }
            uint32_t bh[8][2], bl[8][2];
            #pragma unroll
            for (int nt = 0; nt < 8; nt++) {
                int cb = wn * 64 + nt * 8 + g;
                bh[nt][0] = B2h[kc * 132 + cb];       bl[nt][0] = B2l[kc * 132 + cb];
                bh[nt][1] = B2h[(kc + 4) * 132 + cb]; bl[nt][1] = B2l[(kc + 4) * 132 + cb];
            }
            #pragma unroll
            for (int mt = 0; mt < 2; mt++)
                #pragma unroll
                for (int nt = 0; nt < 8; nt++) {
                    mma_tf32(acc2[mt][nt], ah[mt][0], ah[mt][1], ah[mt][2], ah[mt][3], bh[nt][0], bh[nt][1]);
                    mma_tf32(acc2[mt][nt], al[mt][0], al[mt][1], al[mt][2], al[mt][3], bh[nt][0], bh[nt][1]);
                    mma_tf32(acc2[mt][nt], ah[mt][0], ah[mt][1], ah[mt][2], ah[mt][3], bl[nt][0], bl[nt][1]);
                }
        }
    }

    // ================= epilogue B: grad = W1 @ (sigmoid(a1) * g1) ==========
    {
        float gp[2][2][3];
        #pragma unroll
        for (int mt = 0; mt < 2; mt++)
            #pragma unroll
            for (int o = 0; o < 2; o++)
                gp[mt][o][0] = gp[mt][o][1] = gp[mt][o][2] = 0.f;

        #pragma unroll
        for (int mt = 0; mt < 2; mt++)
            #pragma unroll
            for (int o = 0; o < 2; o++) {
                int rr = wm * 32 + mt * 16 + g + 8 * o;
                float xv = xs[rr], yv = ys[rr], zv = zs[rr];
                #pragma unroll
                for (int nt = 0; nt < 8; nt++)
                    #pragma unroll
                    for (int par = 0; par < 2; par++) {
                        int ii = wn * 64 + nt * 8 + 2 * q + par;
                        float g1 = acc2[mt][nt][o * 2 + par];
                        float w1x = W1s[ii], w1y = W1s[128+ii], w1z = W1s[256+ii];
                        float a1 = fmaf(xv, w1x, fmaf(yv, w1y, fmaf(zv, w1z, b1s[ii])));
                        float gi = g1 * sigmoidf(a1);
                        gp[mt][o][0] = fmaf(w1x, gi, gp[mt][o][0]);
                        gp[mt][o][1] = fmaf(w1y, gi, gp[mt][o][1]);
                        gp[mt][o][2] = fmaf(w1z, gi, gp[mt][o][2]);
                    }
            }
        #pragma unroll
        for (int mt = 0; mt < 2; mt++)
            #pragma unroll
            for (int o = 0; o < 2; o++)
                #pragma unroll
                for (int d = 0; d < 3; d++) {
                    gp[mt][o][d] += __shfl_xor_sync(0xffffffffu, gp[mt][o][d], 1);
                    gp[mt][o][d] += __shfl_xor_sync(0xffffffffu, gp[mt][o][d], 2);
                }
        if (q == 0) {
            #pragma unroll
            for (int mt = 0; mt < 2; mt++)
                #pragma unroll
                for (int o = 0; o < 2; o++) {
                    int rr = wm * 32 + mt * 16 + g + 8 * o;
                    sm[O_GP + (wn * 128 + rr) * 3 + 0] = gp[mt][o][0];
                    sm[O_GP + (wn * 128 + rr) * 3 + 1] = gp[mt][o][1];
                    sm[O_GP + (wn * 128 + rr) * 3 + 2] = gp[mt][o][2];
                }
        }
    }
    __syncthreads();
    if (t < 128) {
        int p = t;
        float gx = sm[O_GP + p*3]     + sm[O_GP + (128+p)*3];
        float gy = sm[O_GP + p*3 + 1] + sm[O_GP + (128+p)*3 + 1];
        float gz = sm[O_GP + p*3 + 2] + sm[O_GP + (128+p)*3 + 2];
        int gidx = blockIdx.x * 128 + p;
        int r = gidx & (NR - 1), s = gidx >> 12;
        int o = 3 * (r * 128 + s);
        grad_out[o] = gx; grad_out[o+1] = gy; grad_out[o+2] = gz;
        g_tc[gidx] = gx * sm[O_DX + p] + gy * sm[O_DY + p] + gz * sm[O_DZ + p];
    }
}

// ---------------- per-ray upsample + sample_pdf ----------------
__global__ void k_upsample(int S, float inv_s, int flag,
                           const float* __restrict__ ro, const float* __restrict__ rd) {
    int r = blockIdx.x * blockDim.x + threadIdx.x;
    if (r >= NR) return;
    const float* zb = flag ? g_z1 : g_z0;
    const float* fb = flag ? g_s1 : g_s0;
    float ox = ro[3 * r], oy = ro[3 * r + 1], oz = ro[3 * r + 2];
    float dx = rd[3 * r], dy = rd[3 * r + 1], dz = rd[3 * r + 2];

    float T = 1.f, wsum = 0.f, cprev = 0.f;
    float z0v = zb[r], f0 = fb[r];
    float px = ox + dx * z0v, py = oy + dy * z0v, pz = oz + dz * z0v;
    float rad_prev = sqrtf(px * px + py * py + pz * pz);
    for (int k = 0; k < S - 1; k++) {
        float z1v = zb[(k + 1) * NR + r], f1 = fb[(k + 1) * NR + r];
        float qx = ox + dx * z1v, qy = oy + dy * z1v, qz = oz + dz * z1v;
        float rad_next = sqrtf(qx * qx + qy * qy + qz * qz);
        float inside = (rad_prev < 1.f || rad_next < 1.f) ? 1.f : 0.f;
        rad_prev = rad_next;
        float c = (f1 - f0) / (z1v - z0v + 1e-5f);
        float cc = fminf((k == 0) ? 0.f : cprev, c);
        cprev = c;
        cc = fminf(fmaxf(cc, -1000.f), 0.f) * inside;
        float midv = 0.5f * (f0 + f1);
        float dd = z1v - z0v;
        float pc = sigmoidf((midv - cc * dd * 0.5f) * inv_s);
        float nc = sigmoidf((midv + cc * dd * 0.5f) * inv_s);
        float a = (pc - nc + 1e-5f) / (pc + 1e-5f);
        float wk = a * T + 1e-5f;
        T *= (1.f - a + 1e-7f);
        g_w[k * NR + r] = wk;
        wsum += wk;
        z0v = z1v; f0 = f1;
    }

    int t = 0;
    float cb = 0.f, run = 0.f;
    z0v = zb[r];
    for (int k = 0; k < S - 1 && t < 16; k++) {
        float z1v = zb[(k + 1) * NR + r];
        run += g_w[k * NR + r] / wsum;
        while (t < 16) {
            float u = (float)(2 * t + 1) * 0.03125f;
            if (!(u < run)) break;
            float denom = run - cb;
            if (denom < 1e-5f) denom = 1.f;
            float tt = (u - cb) / denom;
            g_newz[t * NR + r] = z0v + tt * (z1v - z0v);
            t++;
        }
        cb = run; z0v = z1v;
    }
    float zlast = zb[(S - 1) * NR + r];
    while (t < 16) { g_newz[t * NR + r] = zlast; t++; }
}

// ---------------- per-ray stable merge (streaming, ping-pong) ----------------
__global__ void k_merge(int S, int flag, int last) {
    int r = blockIdx.x * blockDim.x + threadIdx.x;
    if (r >= NR) return;
    const float* zi = flag ? g_z1 : g_z0;
    float* zo = flag ? g_z0 : g_z1;
    const float* si = flag ? g_s1 : g_s0;
    float* so = flag ? g_s0 : g_s1;
    int i = 0, j = 0;
    float zv = zi[r], nv = g_newz[r];
    for (int t = 0; t < S + 16; t++) {
        bool takeold = (j >= 16) || (i < S && zv <= nv);
        if (takeold) {
            zo[t * NR + r] = zv;
            if (!last) so[t * NR + r] = si[i * NR + r];
            i++;
            if (i < S) zv = zi[i * NR + r];
        } else {
            zo[t * NR + r] = nv;
            if (!last) so[t * NR + r] = g_newsdf[j * NR + r];
            j++;
            if (j < 16) nv = g_newz[j * NR + r];
        }
    }
}

// ---------------- per-ray render (depth) ----------------
__global__ void k_render(const float* __restrict__ variance, float* __restrict__ out) {
    int r = blockIdx.x * blockDim.x + threadIdx.x;
    if (r >= NR) return;
    float inv_s = expf(10.f * variance[0]);
    inv_s = fminf(fmaxf(inv_s, 1e-6f), 1e6f);
    float T = 1.f, depth = 0.f;
    for (int k = 0; k < 128; k++) {
        float zk = g_z0[k * NR + r];
        float dist = (k < 127) ? (g_z0[(k + 1) * NR + r] - zk) : 0.03125f;
        float tc = g_tc[k * NR + r];
        float itc = -fmaxf(0.5f - 0.5f * tc, 0.f);   // COS_ANNEAL_RATIO = 0
        float sdf = g_fsdf[k * NR + r];
        float pc = sigmoidf((sdf - itc * dist * 0.5f) * inv_s);
        float nc = sigmoidf((sdf + itc * dist * 0.5f) * inv_s);
        float a = (pc - nc + 1e-5f) / (pc + 1e-5f);
        a = fminf(fmaxf(a, 0.f), 1.f);
        depth += a * T * zk;
        T *= (1.f - a + 1e-7f);
    }
    out[r] = depth;
}

// ---------------- launch ----------------
extern "C" void kernel_launch(void* const* d_in, const int* in_sizes, int n_in,
                              void* d_out, int out_size) {
    const float* rays_o = (const float*)d_in[0];
    const float* rays_d = (const float*)d_in[1];
    const float* near_  = (const float*)d_in[2];
    const float* far_   = (const float*)d_in[3];
    const float* W1 = (const float*)d_in[4];
    const float* b1 = (const float*)d_in[5];
    const float* W2 = (const float*)d_in[6];
    const float* b2 = (const float*)d_in[7];
    const float* W3 = (const float*)d_in[8];
    const float* b3 = (const float*)d_in[9];
    const float* var = (const float*)d_in[10];
    float* out = (float*)d_out;

    cudaFuncSetAttribute(k_mlp_fwd,   cudaFuncAttributeMaxDynamicSharedMemorySize, SMEM_F);
    cudaFuncSetAttribute(k_mlp_final, cudaFuncAttributeMaxDynamicSharedMemorySize, SMEM_FIN);

    // initial coarse sampling: S=64
    k_init_z<<<(NR * 64) / 256, 256>>>(near_, far_);
    k_mlp_fwd<<<(NR * 64) / 128, 256, SMEM_F>>>(W1, b1, W2, b2, W3, b3, rays_o, rays_d, 0);

    // 4 upsample rounds, +16 samples each; z/sdf ping-pong
    for (int i = 0; i < 4; i++) {
        int S = 64 + 16 * i;
        float inv_s = (float)(64 << i);
        int flag = i & 1;
        k_upsample<<<NR / 32, 32>>>(S, inv_s, flag, rays_o, rays_d);
        if (i < 3)
            k_mlp_fwd<<<(NR * 16) / 128, 256, SMEM_F>>>(W1, b1, W2, b2, W3, b3, rays_o, rays_d, 1);
        k_merge<<<NR / 32, 32>>>(S, flag, (i == 3) ? 1 : 0);
    }

    // final: S=128, fused mma.sync tf32 fwd+bwd, then render
    k_mlp_final<<<(NR * 128) / 128, 256, SMEM_FIN>>>(W1, b1, W2, b2, W3, b3,
                                                     rays_o, rays_d, out + NR);
    k_render<<<NR / 32, 32>>>(var, out);
}